// round 1
// baseline (speedup 1.0000x reference)
#include <cuda_runtime.h>
#include <cuda_bf16.h>
#include <math.h>

#define T_LEN    8192
#define VOCAB    50257
#define NCHUNK   8              // key-split factor
#define KCHUNK   (T_LEN / NCHUNK)   // 1024 keys per chunk
#define QBLK     256            // queries per block (1 per thread)

// scratch (device globals; no allocation allowed)
__device__ float4 g_q[T_LEN];                 // pre-scaled q (x,y,z,pad)
__device__ float4 g_k[T_LEN];
__device__ float4 g_v[T_LEN];
__device__ float4 g_part[NCHUNK * T_LEN];     // per-chunk partial (num.xyz, den)

__device__ __forceinline__ float ex2f(float x) {
    float r;
    asm("ex2.approx.f32 %0, %1;" : "=f"(r) : "f"(x));
    return r;
}

// ---------------------------------------------------------------------------
// Kernel 1: gather + posenc + 3x3 projections. q pre-scaled by 3^-1/2 * log2(e)
// so the attention inner loop needs only ex2(dot).
// ---------------------------------------------------------------------------
__global__ void prep_kernel(const int* __restrict__ x,
                            const float* __restrict__ emb,
                            const float* __restrict__ Wk,
                            const float* __restrict__ Wq,
                            const float* __restrict__ Wv) {
    int t = blockIdx.x * blockDim.x + threadIdx.x;
    if (t >= T_LEN) return;

    int xi = x[t];
    xi = min(max(xi, 0), VOCAB - 1);

    // positional encoding — mirror reference fp32 op order: (6.28f * pos) / c
    float a  = 6.28f * (float)t;
    float p0 = emb[xi * 3 + 0] + cosf(a / 25.0f);
    float p1 = emb[xi * 3 + 1] + sinf(a / 25.0f);
    float p2 = emb[xi * 3 + 2] + sinf(a / 5.0f);

    // W is (out,in) row-major; y_i = sum_j W[i][j] * p_j
    const float QSCALE = 0.8329465708f;  // log2(e) / sqrt(3)

    float q0 = fmaf(Wq[0], p0, fmaf(Wq[1], p1, Wq[2] * p2)) * QSCALE;
    float q1 = fmaf(Wq[3], p0, fmaf(Wq[4], p1, Wq[5] * p2)) * QSCALE;
    float q2 = fmaf(Wq[6], p0, fmaf(Wq[7], p1, Wq[8] * p2)) * QSCALE;

    float k0 = fmaf(Wk[0], p0, fmaf(Wk[1], p1, Wk[2] * p2));
    float k1 = fmaf(Wk[3], p0, fmaf(Wk[4], p1, Wk[5] * p2));
    float k2 = fmaf(Wk[6], p0, fmaf(Wk[7], p1, Wk[8] * p2));

    float v0 = fmaf(Wv[0], p0, fmaf(Wv[1], p1, Wv[2] * p2));
    float v1 = fmaf(Wv[3], p0, fmaf(Wv[4], p1, Wv[5] * p2));
    float v2 = fmaf(Wv[6], p0, fmaf(Wv[7], p1, Wv[8] * p2));

    g_q[t] = make_float4(q0, q1, q2, 0.0f);
    g_k[t] = make_float4(k0, k1, k2, 0.0f);
    g_v[t] = make_float4(v0, v1, v2, 0.0f);
}

// ---------------------------------------------------------------------------
// Kernel 2: fused attention, no-max softmax (scores bounded ~|20| << 88).
// grid = (T/QBLK, NCHUNK). Each CTA: QBLK queries x KCHUNK keys.
// k,v chunk staged in smem; per-key reads are warp-uniform (broadcast).
// ---------------------------------------------------------------------------
__global__ __launch_bounds__(QBLK)
void attn_kernel() {
    __shared__ float4 sk[KCHUNK];
    __shared__ float4 sv[KCHUNK];

    const int tid   = threadIdx.x;
    const int kbase = blockIdx.y * KCHUNK;

    #pragma unroll
    for (int i = tid; i < KCHUNK; i += QBLK) {
        sk[i] = g_k[kbase + i];
        sv[i] = g_v[kbase + i];
    }
    __syncthreads();

    const int t = blockIdx.x * QBLK + tid;
    const float4 q = g_q[t];

    float den = 0.0f, a0 = 0.0f, a1 = 0.0f, a2 = 0.0f;

    #pragma unroll 8
    for (int j = 0; j < KCHUNK; ++j) {
        float4 k = sk[j];
        float s  = fmaf(q.x, k.x, fmaf(q.y, k.y, q.z * k.z));
        float e  = ex2f(s);                 // exp(score/sqrt(3)) via folded scale
        float4 v = sv[j];
        den += e;
        a0 = fmaf(e, v.x, a0);
        a1 = fmaf(e, v.y, a1);
        a2 = fmaf(e, v.z, a2);
    }

    g_part[blockIdx.y * T_LEN + t] = make_float4(a0, a1, a2, den);
}

// ---------------------------------------------------------------------------
// Kernel 3: deterministic fixed-order reduce over NCHUNK partials + divide.
// ---------------------------------------------------------------------------
__global__ void reduce_kernel(float* __restrict__ out) {
    int t = blockIdx.x * blockDim.x + threadIdx.x;
    if (t >= T_LEN) return;

    float a0 = 0.0f, a1 = 0.0f, a2 = 0.0f, den = 0.0f;
    #pragma unroll
    for (int s = 0; s < NCHUNK; ++s) {
        float4 p = g_part[s * T_LEN + t];
        a0 += p.x; a1 += p.y; a2 += p.z; den += p.w;
    }
    float inv = 1.0f / den;
    out[t * 3 + 0] = a0 * inv;
    out[t * 3 + 1] = a1 * inv;
    out[t * 3 + 2] = a2 * inv;
}

extern "C" void kernel_launch(void* const* d_in, const int* in_sizes, int n_in,
                              void* d_out, int out_size) {
    const int*   x   = (const int*)  d_in[0];
    const float* emb = (const float*)d_in[1];
    const float* Wk  = (const float*)d_in[2];
    const float* Wq  = (const float*)d_in[3];
    const float* Wv  = (const float*)d_in[4];
    float* out = (float*)d_out;

    prep_kernel<<<T_LEN / 256, 256>>>(x, emb, Wk, Wq, Wv);
    attn_kernel<<<dim3(T_LEN / QBLK, NCHUNK), QBLK>>>();
    reduce_kernel<<<T_LEN / 256, 256>>>(out);
}

// round 2
// speedup vs baseline: 1.1499x; 1.1499x over previous
#include <cuda_runtime.h>
#include <cuda_bf16.h>
#include <math.h>

#define T_LEN    8192
#define VOCAB    50257
#define NCHUNK   37             // key-split: 16 qblocks x 37 chunks = 592 CTAs = 4/SM exactly
#define NQBLK    16
#define QBLK     512            // queries per CTA
#define NTHREADS 128            // 4 queries per thread
#define QPT      4
#define KMAX     222            // ceil(8192/37)

// scratch (device globals; no allocation allowed)
__device__ float4 g_q[T_LEN];                 // pre-scaled q (x,y,z,pad)
__device__ float4 g_k[T_LEN];
__device__ float4 g_v[T_LEN];
__device__ float4 g_part[NCHUNK * T_LEN];     // per-chunk partial (num.xyz, den)

__device__ __forceinline__ float ex2f(float x) {
    float r;
    asm("ex2.approx.f32 %0, %1;" : "=f"(r) : "f"(x));
    return r;
}

// ---------------------------------------------------------------------------
// Kernel 1: gather + posenc + 3x3 projections. q pre-scaled by 3^-1/2 * log2(e)
// so the attention inner loop needs only ex2(dot).
// ---------------------------------------------------------------------------
__global__ void prep_kernel(const int* __restrict__ x,
                            const float* __restrict__ emb,
                            const float* __restrict__ Wk,
                            const float* __restrict__ Wq,
                            const float* __restrict__ Wv) {
    int t = blockIdx.x * blockDim.x + threadIdx.x;
    if (t >= T_LEN) return;

    int xi = x[t];
    xi = min(max(xi, 0), VOCAB - 1);

    // positional encoding — mirror reference fp32 op order: (6.28f * pos) / c
    float a  = 6.28f * (float)t;
    float p0 = emb[xi * 3 + 0] + cosf(a / 25.0f);
    float p1 = emb[xi * 3 + 1] + sinf(a / 25.0f);
    float p2 = emb[xi * 3 + 2] + sinf(a / 5.0f);

    const float QSCALE = 0.8329465708f;  // log2(e) / sqrt(3)

    float q0 = fmaf(Wq[0], p0, fmaf(Wq[1], p1, Wq[2] * p2)) * QSCALE;
    float q1 = fmaf(Wq[3], p0, fmaf(Wq[4], p1, Wq[5] * p2)) * QSCALE;
    float q2 = fmaf(Wq[6], p0, fmaf(Wq[7], p1, Wq[8] * p2)) * QSCALE;

    float k0 = fmaf(Wk[0], p0, fmaf(Wk[1], p1, Wk[2] * p2));
    float k1 = fmaf(Wk[3], p0, fmaf(Wk[4], p1, Wk[5] * p2));
    float k2 = fmaf(Wk[6], p0, fmaf(Wk[7], p1, Wk[8] * p2));

    float v0 = fmaf(Wv[0], p0, fmaf(Wv[1], p1, Wv[2] * p2));
    float v1 = fmaf(Wv[3], p0, fmaf(Wv[4], p1, Wv[5] * p2));
    float v2 = fmaf(Wv[6], p0, fmaf(Wv[7], p1, Wv[8] * p2));

    g_q[t] = make_float4(q0, q1, q2, 0.0f);
    g_k[t] = make_float4(k0, k1, k2, 0.0f);
    g_v[t] = make_float4(v0, v1, v2, 0.0f);
}

// ---------------------------------------------------------------------------
// Kernel 2: fused attention, no-max softmax (scores bounded << 88).
// grid = (NQBLK, NCHUNK) = (16, 37) = 592 CTAs = exactly 4 CTAs/SM, one wave.
// Each CTA: 512 queries (4 per thread) x ~221 keys (chunk staged in smem).
// ---------------------------------------------------------------------------
__global__ __launch_bounds__(NTHREADS)
void attn_kernel() {
    __shared__ float4 sk[KMAX];
    __shared__ float4 sv[KMAX];

    const int tid  = threadIdx.x;
    const int c    = blockIdx.y;
    const int kbeg = (c * T_LEN) / NCHUNK;
    const int kend = ((c + 1) * T_LEN) / NCHUNK;
    const int klen = kend - kbeg;

    for (int i = tid; i < klen; i += NTHREADS) {
        sk[i] = g_k[kbeg + i];
        sv[i] = g_v[kbeg + i];
    }
    __syncthreads();

    const int qbase = blockIdx.x * QBLK + tid;
    float4 q[QPT];
    #pragma unroll
    for (int u = 0; u < QPT; ++u) q[u] = g_q[qbase + u * NTHREADS];

    float den[QPT], a0[QPT], a1[QPT], a2[QPT];
    #pragma unroll
    for (int u = 0; u < QPT; ++u) { den[u] = a0[u] = a1[u] = a2[u] = 0.0f; }

    #pragma unroll 4
    for (int j = 0; j < klen; ++j) {
        float4 k = sk[j];
        float4 v = sv[j];
        #pragma unroll
        for (int u = 0; u < QPT; ++u) {
            float s = fmaf(q[u].x, k.x, fmaf(q[u].y, k.y, q[u].z * k.z));
            float e = ex2f(s);
            den[u] += e;
            a0[u] = fmaf(e, v.x, a0[u]);
            a1[u] = fmaf(e, v.y, a1[u]);
            a2[u] = fmaf(e, v.z, a2[u]);
        }
    }

    #pragma unroll
    for (int u = 0; u < QPT; ++u)
        g_part[c * T_LEN + qbase + u * NTHREADS] =
            make_float4(a0[u], a1[u], a2[u], den[u]);
}

// ---------------------------------------------------------------------------
// Kernel 3: deterministic fixed-order reduce over NCHUNK partials + divide.
// ---------------------------------------------------------------------------
__global__ void reduce_kernel(float* __restrict__ out) {
    int t = blockIdx.x * blockDim.x + threadIdx.x;
    if (t >= T_LEN) return;

    float a0 = 0.0f, a1 = 0.0f, a2 = 0.0f, den = 0.0f;
    #pragma unroll
    for (int s = 0; s < NCHUNK; ++s) {
        float4 p = g_part[s * T_LEN + t];
        a0 += p.x; a1 += p.y; a2 += p.z; den += p.w;
    }
    float inv = 1.0f / den;
    out[t * 3 + 0] = a0 * inv;
    out[t * 3 + 1] = a1 * inv;
    out[t * 3 + 2] = a2 * inv;
}

extern "C" void kernel_launch(void* const* d_in, const int* in_sizes, int n_in,
                              void* d_out, int out_size) {
    const int*   x   = (const int*)  d_in[0];
    const float* emb = (const float*)d_in[1];
    const float* Wk  = (const float*)d_in[2];
    const float* Wq  = (const float*)d_in[3];
    const float* Wv  = (const float*)d_in[4];
    float* out = (float*)d_out;

    prep_kernel<<<T_LEN / 256, 256>>>(x, emb, Wk, Wq, Wv);
    attn_kernel<<<dim3(NQBLK, NCHUNK), NTHREADS>>>();
    reduce_kernel<<<T_LEN / 256, 256>>>(out);
}

// round 3
// speedup vs baseline: 1.1508x; 1.0008x over previous
#include <cuda_runtime.h>
#include <cuda_bf16.h>
#include <math.h>

#define T_LEN    8192
#define VOCAB    50257
#define NCHUNK   37             // 16 qblocks x 37 chunks = 592 CTAs = exactly 4/SM, one wave
#define NQBLK    16
#define QBLK     512            // queries per CTA
#define NTHREADS 128
#define QPT      4              // queries per thread = 2 packed f32x2 pairs
#define KMAX     222            // ceil(8192/37)

typedef unsigned long long ull;

// scratch (device globals; no allocation allowed)
__device__ float4 g_q[T_LEN];                  // pre-scaled q
__device__ ulonglong2 g_A[T_LEN];              // ((kx,kx),(ky,ky)) packed f32x2
__device__ ulonglong2 g_B[T_LEN];              // ((kz,kz),(vx,vx))
__device__ ulonglong2 g_C[T_LEN];              // ((vy,vy),(vz,vz))
__device__ float4 g_part[NCHUNK * T_LEN];      // per-chunk partial (num.xyz, den)

__device__ __forceinline__ float ex2f(float x) {
    float r; asm("ex2.approx.f32 %0, %1;" : "=f"(r) : "f"(x)); return r;
}
__device__ __forceinline__ ull fma2(ull a, ull b, ull c) {
    ull r; asm("fma.rn.f32x2 %0, %1, %2, %3;" : "=l"(r) : "l"(a), "l"(b), "l"(c)); return r;
}
__device__ __forceinline__ ull mul2(ull a, ull b) {
    ull r; asm("mul.rn.f32x2 %0, %1, %2;" : "=l"(r) : "l"(a), "l"(b)); return r;
}
__device__ __forceinline__ ull add2(ull a, ull b) {
    ull r; asm("add.rn.f32x2 %0, %1, %2;" : "=l"(r) : "l"(a), "l"(b)); return r;
}
__device__ __forceinline__ ull pack2(float lo, float hi) {
    ull r; asm("mov.b64 %0, {%1, %2};" : "=l"(r) : "f"(lo), "f"(hi)); return r;
}
__device__ __forceinline__ void unpack2(ull v, float& lo, float& hi) {
    asm("mov.b64 {%0, %1}, %2;" : "=f"(lo), "=f"(hi) : "l"(v));
}
__device__ __forceinline__ ull dup2(float a) {
    unsigned u = __float_as_uint(a);
    return ((ull)u << 32) | u;
}

// ---------------------------------------------------------------------------
// Kernel 1: gather + posenc + 3x3 projections; emit duplicated-pair k/v layout.
// q pre-scaled by log2(e)/sqrt(3) so the attention loop is ex2(dot).
// ---------------------------------------------------------------------------
__global__ __launch_bounds__(128)
void prep_kernel(const int* __restrict__ x,
                 const float* __restrict__ emb,
                 const float* __restrict__ Wk,
                 const float* __restrict__ Wq,
                 const float* __restrict__ Wv) {
    int t = blockIdx.x * blockDim.x + threadIdx.x;
    if (t >= T_LEN) return;

    int xi = x[t];
    xi = min(max(xi, 0), VOCAB - 1);

    float a  = 6.28f * (float)t;
    float p0 = emb[xi * 3 + 0] + cosf(a / 25.0f);
    float p1 = emb[xi * 3 + 1] + sinf(a / 25.0f);
    float p2 = emb[xi * 3 + 2] + sinf(a / 5.0f);

    const float QSCALE = 0.8329465708f;  // log2(e) / sqrt(3)

    float q0 = fmaf(Wq[0], p0, fmaf(Wq[1], p1, Wq[2] * p2)) * QSCALE;
    float q1 = fmaf(Wq[3], p0, fmaf(Wq[4], p1, Wq[5] * p2)) * QSCALE;
    float q2 = fmaf(Wq[6], p0, fmaf(Wq[7], p1, Wq[8] * p2)) * QSCALE;

    float k0 = fmaf(Wk[0], p0, fmaf(Wk[1], p1, Wk[2] * p2));
    float k1 = fmaf(Wk[3], p0, fmaf(Wk[4], p1, Wk[5] * p2));
    float k2 = fmaf(Wk[6], p0, fmaf(Wk[7], p1, Wk[8] * p2));

    float v0 = fmaf(Wv[0], p0, fmaf(Wv[1], p1, Wv[2] * p2));
    float v1 = fmaf(Wv[3], p0, fmaf(Wv[4], p1, Wv[5] * p2));
    float v2 = fmaf(Wv[6], p0, fmaf(Wv[7], p1, Wv[8] * p2));

    g_q[t] = make_float4(q0, q1, q2, 0.0f);
    g_A[t] = make_ulonglong2(dup2(k0), dup2(k1));
    g_B[t] = make_ulonglong2(dup2(k2), dup2(v0));
    g_C[t] = make_ulonglong2(dup2(v1), dup2(v2));
}

// ---------------------------------------------------------------------------
// Kernel 2: fused attention, no-max softmax, packed f32x2 math.
// grid = (16, 37) = 592 CTAs = 4/SM. Each thread: 4 queries = 2 f32x2 pairs.
// ---------------------------------------------------------------------------
__global__ __launch_bounds__(NTHREADS)
void attn_kernel() {
    __shared__ ulonglong2 sA[KMAX];
    __shared__ ulonglong2 sB[KMAX];
    __shared__ ulonglong2 sC[KMAX];

    const int tid  = threadIdx.x;
    const int c    = blockIdx.y;
    const int kbeg = (c * T_LEN) / NCHUNK;
    const int kend = ((c + 1) * T_LEN) / NCHUNK;
    const int klen = kend - kbeg;

    for (int i = tid; i < klen; i += NTHREADS) {
        sA[i] = g_A[kbeg + i];
        sB[i] = g_B[kbeg + i];
        sC[i] = g_C[kbeg + i];
    }
    __syncthreads();

    const int qbase = blockIdx.x * QBLK + tid;
    // pair p holds queries (qbase + p*128, qbase + (p+2)*128)
    ull qx2[2], qy2[2], qz2[2];
    #pragma unroll
    for (int p = 0; p < 2; ++p) {
        float4 qa = g_q[qbase + p * NTHREADS];
        float4 qb = g_q[qbase + (p + 2) * NTHREADS];
        qx2[p] = pack2(qa.x, qb.x);
        qy2[p] = pack2(qa.y, qb.y);
        qz2[p] = pack2(qa.z, qb.z);
    }

    ull den2[2], a0[2], a1[2], a2[2];
    const ull z = 0ull;
    #pragma unroll
    for (int p = 0; p < 2; ++p) { den2[p] = a0[p] = a1[p] = a2[p] = z; }

    #pragma unroll 2
    for (int j = 0; j < klen; ++j) {
        ulonglong2 A = sA[j];   // (kx,kx),(ky,ky)
        ulonglong2 B = sB[j];   // (kz,kz),(vx,vx)
        ulonglong2 C = sC[j];   // (vy,vy),(vz,vz)
        #pragma unroll
        for (int p = 0; p < 2; ++p) {
            ull s2 = fma2(qx2[p], A.x, fma2(qy2[p], A.y, mul2(qz2[p], B.x)));
            float lo, hi; unpack2(s2, lo, hi);
            ull e2 = pack2(ex2f(lo), ex2f(hi));
            den2[p] = add2(den2[p], e2);
            a0[p] = fma2(e2, B.y, a0[p]);
            a1[p] = fma2(e2, C.x, a1[p]);
            a2[p] = fma2(e2, C.y, a2[p]);
        }
    }

    #pragma unroll
    for (int p = 0; p < 2; ++p) {
        float d_a, d_b, x_a, x_b, y_a, y_b, z_a, z_b;
        unpack2(den2[p], d_a, d_b);
        unpack2(a0[p],   x_a, x_b);
        unpack2(a1[p],   y_a, y_b);
        unpack2(a2[p],   z_a, z_b);
        g_part[c * T_LEN + qbase + p * NTHREADS]       = make_float4(x_a, y_a, z_a, d_a);
        g_part[c * T_LEN + qbase + (p + 2) * NTHREADS] = make_float4(x_b, y_b, z_b, d_b);
    }
}

// ---------------------------------------------------------------------------
// Kernel 3: deterministic fixed-order reduce over NCHUNK partials + divide.
// ---------------------------------------------------------------------------
__global__ void reduce_kernel(float* __restrict__ out) {
    int t = blockIdx.x * blockDim.x + threadIdx.x;
    if (t >= T_LEN) return;

    float a0 = 0.0f, a1 = 0.0f, a2 = 0.0f, den = 0.0f;
    #pragma unroll
    for (int s = 0; s < NCHUNK; ++s) {
        float4 p = g_part[s * T_LEN + t];
        a0 += p.x; a1 += p.y; a2 += p.z; den += p.w;
    }
    float inv = 1.0f / den;
    out[t * 3 + 0] = a0 * inv;
    out[t * 3 + 1] = a1 * inv;
    out[t * 3 + 2] = a2 * inv;
}

extern "C" void kernel_launch(void* const* d_in, const int* in_sizes, int n_in,
                              void* d_out, int out_size) {
    const int*   x   = (const int*)  d_in[0];
    const float* emb = (const float*)d_in[1];
    const float* Wk  = (const float*)d_in[2];
    const float* Wq  = (const float*)d_in[3];
    const float* Wv  = (const float*)d_in[4];
    float* out = (float*)d_out;

    prep_kernel<<<T_LEN / 128, 128>>>(x, emb, Wk, Wq, Wv);
    attn_kernel<<<dim3(NQBLK, NCHUNK), NTHREADS>>>();
    reduce_kernel<<<T_LEN / 256, 256>>>(out);
}